// round 17
// baseline (speedup 1.0000x reference)
#include <cuda_runtime.h>
#include <cuda_bf16.h>

// HOG: gx,gy = sobel cross-correlation (zero pad), mag = sqrt(gx^2+gy^2),
// ang = |atan2(gx, gy)| in [0, pi], bin = floor(ang*8/pi) in 0..8,
// out[b][bin][cy][cx] = sum of mag over the 8x8 cell.
//
// Binning without atan2: ang >= k*pi/8  <=>  cot(k*pi/8)*|gx| - gy >= 0.
// Predicates monotone in k -> prefix sums A[k], per-bin = A[k]-A[k+1].
// Bin 8 (ang == pi) iff gx==0 && gy<=0 (gy==0 adds mag==0; form shares A4's
// predicate via FSETP.EQ.AND).
//
// R17: single-wave grid. 1 thread = TWO vertically adjacent 8x8 cells,
// 128-thread blocks -> 1024 blocks total; at ~50 regs, 9-10 blocks/SM fit, so
// ALL blocks are resident at once: no wave quantization, no end-of-grid drain
// (R16's occ showed ~23% slot-time lost to drain). Both the cell loop and the
// half loop use #pragma unroll 1 (R16's register-pressure trick, regs=48).
// Per-cell pixel math byte-identical to the R16 winner.

__device__ __forceinline__ float fsqrt_approx(float v) {
    float r;
    asm("sqrt.approx.f32 %0, %1;" : "=f"(r) : "f"(v));
    return r;
}

__global__ void __launch_bounds__(128) hog_kernel(const float* __restrict__ x,
                                                  float* __restrict__ out) {
    const int t    = blockIdx.x * 128 + threadIdx.x;
    const int cx   = t & 63;
    const int pair = (t >> 6) & 31;     // vertical cell-pair index
    const int b    = t >> 11;
    const float* img = x + (size_t)b * (512 * 512);

#pragma unroll 1
    for (int c = 0; c < 2; c++) {
        const int cy = (pair << 1) + c;
        const int R  = cy << 3;

        // Prefix accumulators: A0 = sum(mag); Ak = sum(mag | ang >= k*pi/8)
        float A0 = 0.f, A1 = 0.f, A2 = 0.f, A3 = 0.f, A4 = 0.f,
              A5 = 0.f, A6 = 0.f, A7 = 0.f, A8 = 0.f;

#pragma unroll 1
        for (int hf = 0; hf < 2; hf++) {
            const int Ch = (cx << 3) + (hf << 2);   // first column of this half
            // left halo col Ch-1 outside image only for hf==0 && cx==0;
            // right halo col Ch+4 outside only for hf==1 && cx==63.
            const bool okL = (hf == 1) || (cx > 0);
            const bool okR = (hf == 0) || (cx < 63);

            // rolling horizontal passes for 3 raw rows over 4 columns:
            // hd[i] = r[Ch+i+1]-r[Ch+i-1], hs[i] = r[Ch+i-1]+2r[Ch+i]+r[Ch+i+1]
            float hd[3][4], hs[3][4];

#define LOAD_H(RI, rrow)                                                       \
            {                                                                  \
                const float* _p = img + (rrow) * 512 + Ch;                     \
                const float _eL = okL ? _p[-1] : 0.f;                          \
                const float4 _v = *(const float4*)(_p);                        \
                const float _eR = okR ? _p[4] : 0.f;                           \
                hd[RI][0] = _v.y - _eL;                                        \
                hd[RI][1] = _v.z - _v.x;                                       \
                hd[RI][2] = _v.w - _v.y;                                       \
                hd[RI][3] = _eR - _v.z;                                        \
                hs[RI][0] = fmaf(2.f, _v.x, _eL + _v.y);                       \
                hs[RI][1] = fmaf(2.f, _v.y, _v.x + _v.z);                      \
                hs[RI][2] = fmaf(2.f, _v.z, _v.y + _v.w);                      \
                hs[RI][3] = fmaf(2.f, _v.w, _v.z + _eR);                       \
            }

#define ZERO_H(RI)                                                             \
            {                                                                  \
                _Pragma("unroll")                                              \
                for (int _j = 0; _j < 4; _j++) { hd[RI][_j] = 0.f; hs[RI][_j] = 0.f; } \
            }

            // prologue: row R-1 (OOB only for cy==0), row R (always valid)
            if (cy > 0) { LOAD_H(0, R - 1); } else { ZERO_H(0); }
            LOAD_H(1, R);

#pragma unroll
            for (int rr = 0; rr < 8; rr++) {
                const int ia = rr % 3;          // row R+rr-1 (top)
                const int ib = (rr + 1) % 3;    // row R+rr   (mid)
                const int ic = (rr + 2) % 3;    // row R+rr+1 (bottom)
                if (rr < 7) {
                    LOAD_H(ic, R + rr + 1);     // rows R+1..R+7 always in range
                } else {
                    if (cy < 63) { LOAD_H(ic, R + 8); } else { ZERO_H(ic); }
                }

#pragma unroll
                for (int i = 0; i < 4; i++) {
                    // gx = (right-left) smoothed vertically;
                    // gy = (bottom-top) smoothed horizontally
                    const float gx = fmaf(2.f, hd[ib][i], hd[ia][i] + hd[ic][i]);
                    const float gy = hs[ic][i] - hs[ia][i];
                    const float a  = fabsf(gx);
                    const float mag = fsqrt_approx(fmaf(gx, gx, gy * gy));
                    A0 += mag;
                    // cot(k*pi/8), k=1..7: 2.41421, 1, 0.41421, 0, -0.41421, -1, -2.41421
                    if (fmaf(a,  2.414213562373095f, -gy) >= 0.f)  A1 += mag;
                    if (a >= gy)                                   A2 += mag;
                    if (fmaf(a,  0.4142135623730951f, -gy) >= 0.f) A3 += mag;
                    if (gy <= 0.f)                                 A4 += mag;
                    if (fmaf(a, -0.4142135623730951f, -gy) >= 0.f) A5 += mag;
                    if (gy <= -a)                                  A6 += mag;
                    if (fmaf(a, -2.414213562373095f, -gy) >= 0.f)  A7 += mag;
                    if (gx == 0.f && gy <= 0.f)                    A8 += mag; // ang == pi
                }
            }
#undef LOAD_H
#undef ZERO_H
        }

        // out[b][k][cy][cx], per-bin value = A[k] - A[k+1]
        float* o = out + (size_t)b * (9 * 4096) + (cy << 6) + cx;
        o[0 * 4096] = A0 - A1;
        o[1 * 4096] = A1 - A2;
        o[2 * 4096] = A2 - A3;
        o[3 * 4096] = A3 - A4;
        o[4 * 4096] = A4 - A5;
        o[5 * 4096] = A5 - A6;
        o[6 * 4096] = A6 - A7;
        o[7 * 4096] = A7 - A8;
        o[8 * 4096] = A8;
    }
}

extern "C" void kernel_launch(void* const* d_in, const int* in_sizes, int n_in,
                              void* d_out, int out_size) {
    const float* x = (const float*)d_in[0];
    float* out = (float*)d_out;
    // 64 batches * 64 cx * 32 cell-pairs = 131072 threads, 128/block
    hog_kernel<<<1024, 128>>>(x, out);
}